// round 2
// baseline (speedup 1.0000x reference)
#include <cuda_runtime.h>
#include <math.h>

#define NB      64
#define SHIFT   150
#define LEN     200
#define NH      128           // only first 128 bins survive the slice
#define TT      64            // t-tile per block
#define KC      8             // K chunk
#define SIGTILE (SHIFT*(TT-1)+LEN)   // 9650
#define EPSF    1e-7f
#define INV_LN10 0.4342944819032518f

// scratch (device globals — no allocation allowed)
__device__ float g_mu[NB];
__device__ float g_sd[NB];
__device__ __align__(16) float g_ktr[LEN*NH];   // [l][n] transposed real kernel (n<128)
__device__ __align__(16) float g_kti[LEN*NH];   // [l][n] transposed imag kernel

// ---------------------------------------------------------------------------
// Pass A: per-batch mean / population std
// ---------------------------------------------------------------------------
__global__ void stats_kernel(const float* __restrict__ x, int S) {
    int b = blockIdx.x;
    const float* xb = x + (size_t)b * S;
    float sum = 0.f, sq = 0.f;

    // scalar prologue up to 16-byte alignment (b*S may be odd multiple of 8B)
    int pre = (int)(((16u - (unsigned)((size_t)xb & 15u)) & 15u) >> 2);
    if (pre > S) pre = S;
    for (int i = threadIdx.x; i < pre; i += blockDim.x) {
        float v = xb[i]; sum += v; sq += v*v;
    }
    int rem = S - pre;
    int n4  = rem >> 2;
    const float4* x4 = (const float4*)(xb + pre);
    for (int i = threadIdx.x; i < n4; i += blockDim.x) {
        float4 v = x4[i];
        sum += v.x + v.y + v.z + v.w;
        sq  += v.x*v.x + v.y*v.y + v.z*v.z + v.w*v.w;
    }
    for (int i = pre + (n4 << 2) + threadIdx.x; i < S; i += blockDim.x) {
        float v = xb[i]; sum += v; sq += v*v;
    }

    __shared__ float ssum[32], ssq[32];
    #pragma unroll
    for (int o = 16; o > 0; o >>= 1) {
        sum += __shfl_xor_sync(~0u, sum, o);
        sq  += __shfl_xor_sync(~0u, sq,  o);
    }
    int w = threadIdx.x >> 5, ln = threadIdx.x & 31;
    if (ln == 0) { ssum[w] = sum; ssq[w] = sq; }
    __syncthreads();
    if (w == 0) {
        int nw = blockDim.x >> 5;
        sum = (ln < nw) ? ssum[ln] : 0.f;
        sq  = (ln < nw) ? ssq[ln]  : 0.f;
        #pragma unroll
        for (int o = 16; o > 0; o >>= 1) {
            sum += __shfl_xor_sync(~0u, sum, o);
            sq  += __shfl_xor_sync(~0u, sq,  o);
        }
        if (ln == 0) {
            float mu  = sum / (float)S;
            float var = sq / (float)S - mu * mu;
            g_mu[b] = mu;
            g_sd[b] = sqrtf(fmaxf(var, 0.f));
        }
    }
}

// ---------------------------------------------------------------------------
// One-time kernel transpose: [n][l] -> [l][n], n < 128 only
// ---------------------------------------------------------------------------
__global__ void transpose_kernel(const float* __restrict__ kr,
                                 const float* __restrict__ ki) {
    int idx = blockIdx.x * blockDim.x + threadIdx.x;
    if (idx >= LEN * NH) return;
    int n = idx % NH, l = idx / NH;        // write coalesced in n
    g_ktr[idx] = kr[n * LEN + l];
    g_kti[idx] = ki[n * LEN + l];
}

// ---------------------------------------------------------------------------
// Pass B: fused frame + DFT(128 bins) + mag + log10 + per-t bin-normalize
// grid = (T/TT, B), 256 threads.
// Per-thread register tile: 4 n  x  8 t (re+im accumulators).
//   tn = tid&31  -> n = tn*4 + i   (warp lanes cover all 128 bins)
//   g  = tid>>5  -> t = g*8 + j    (each warp owns 8 complete t's)
// ---------------------------------------------------------------------------
__global__ void __launch_bounds__(256)
dft_kernel(const float* __restrict__ x, float* __restrict__ out, int S, int T) {
    __shared__ __align__(16) float s_sig[SIGTILE + 14];  // 9664; reused as vals[t][132]
    __shared__ __align__(16) float s_kr[KC * NH];
    __shared__ __align__(16) float s_ki[KC * NH];

    const int b   = blockIdx.y;
    const int t0  = blockIdx.x * TT;
    const int tid = threadIdx.x;

    const float mu  = g_mu[b];
    const float inv = 1.f / (g_sd[b] + EPSF);

    const float* base = x + (size_t)b * S + (size_t)t0 * SHIFT;
    for (int i = tid; i < SIGTILE; i += 256)
        s_sig[i] = (base[i] - mu) * inv;
    __syncthreads();

    const int tn = tid & 31;
    const int g  = tid >> 5;

    float aR[4][8], aI[4][8];
    #pragma unroll
    for (int i = 0; i < 4; i++)
        #pragma unroll
        for (int j = 0; j < 8; j++) { aR[i][j] = 0.f; aI[i][j] = 0.f; }

    for (int lc = 0; lc < LEN; lc += KC) {
        ((float4*)s_kr)[tid] = ((const float4*)(g_ktr + lc * NH))[tid];
        ((float4*)s_ki)[tid] = ((const float4*)(g_kti + lc * NH))[tid];
        __syncthreads();
        #pragma unroll
        for (int l = 0; l < KC; l++) {
            const float4 kr4 = *(const float4*)&s_kr[l * NH + tn * 4];
            const float4 ki4 = *(const float4*)&s_ki[l * NH + tn * 4];
            const int ls = lc + l;
            #pragma unroll
            for (int j = 0; j < 8; j++) {
                const float s = s_sig[SHIFT * (g * 8 + j) + ls];  // warp broadcast
                aR[0][j] += kr4.x * s;
                aR[1][j] += kr4.y * s;
                aR[2][j] += kr4.z * s;
                aR[3][j] += kr4.w * s;
                aI[0][j] += ki4.x * s;
                aI[1][j] += ki4.y * s;
                aI[2][j] += ki4.z * s;
                aI[3][j] += ki4.w * s;
            }
        }
        __syncthreads();
    }

    // epilogue: mag -> log10 -> normalize over the 128 bins of each t
    float* vals = s_sig;   // reuse as [t][132] (padded vs bank conflicts)
    #pragma unroll
    for (int j = 0; j < 8; j++) {
        const int tl = g * 8 + j;
        float v[4];
        #pragma unroll
        for (int i = 0; i < 4; i++) {
            float m2 = aR[i][j] * aR[i][j] + aI[i][j] * aI[i][j];
            float m  = sqrtf(m2);
            v[i] = logf(fmaxf(m, EPSF)) * INV_LN10;
        }
        float p = v[0] + v[1] + v[2] + v[3];
        float q = v[0]*v[0] + v[1]*v[1] + v[2]*v[2] + v[3]*v[3];
        #pragma unroll
        for (int o = 16; o > 0; o >>= 1) {
            p += __shfl_xor_sync(~0u, p, o);
            q += __shfl_xor_sync(~0u, q, o);
        }
        const float mean = p * (1.f / NH);
        const float var  = q * (1.f / NH) - mean * mean;
        const float invn = 1.f / (sqrtf(fmaxf(var, 0.f)) + EPSF);
        float4 w = make_float4((v[0] - mean) * invn, (v[1] - mean) * invn,
                               (v[2] - mean) * invn, (v[3] - mean) * invn);
        *(float4*)&vals[tl * 132 + tn * 4] = w;
    }
    __syncthreads();

    // coalesced store: out[b][n][t0 + tc]
    for (int k = tid; k < NH * TT; k += 256) {
        const int n  = k >> 6;
        const int tc = k & 63;
        out[((size_t)(b * NH + n)) * T + t0 + tc] = vals[tc * 132 + n];
    }
}

// ---------------------------------------------------------------------------
extern "C" void kernel_launch(void* const* d_in, const int* in_sizes, int n_in,
                              void* d_out, int out_size) {
    const float* x  = (const float*)d_in[0];
    const float* kr = (const float*)d_in[1];
    const float* ki = (const float*)d_in[2];
    float* out = (float*)d_out;

    const int S = in_sizes[0] / NB;            // 480050
    const int T = (S - LEN) / SHIFT + 1;       // 3200

    stats_kernel<<<NB, 1024>>>(x, S);
    transpose_kernel<<<(LEN * NH + 255) / 256, 256>>>(kr, ki);
    dft_kernel<<<dim3(T / TT, NB), 256>>>(x, out, S, T);
}

// round 3
// speedup vs baseline: 1.0690x; 1.0690x over previous
#include <cuda_runtime.h>
#include <math.h>

#define NB      64
#define SHIFT   150
#define LEN     200
#define NH      128           // only first 128 bins survive the slice
#define TT      64            // t-tile per block
#define KC      8             // K chunk
#define NCHUNK  8             // stats chunks per batch
#define SIGTILE (SHIFT*(TT-1)+LEN)   // 9650
#define EPSF    1e-7f
#define INV_LN10 0.4342944819032518f

typedef unsigned long long ull;

__device__ __forceinline__ void ffma2(ull &d, ull a, ull b) {
    asm("fma.rn.f32x2 %0, %1, %2, %0;" : "+l"(d) : "l"(a), "l"(b));
}
__device__ __forceinline__ ull dup2(float s) {
    ull r; asm("mov.b64 %0, {%1, %1};" : "=l"(r) : "f"(s)); return r;
}
__device__ __forceinline__ float2 unpack2(ull v) {
    float2 r; asm("mov.b64 {%0, %1}, %2;" : "=f"(r.x), "=f"(r.y) : "l"(v)); return r;
}

// scratch (device globals — no allocation allowed)
__device__ float g_mu[NB];
__device__ float g_sd[NB];
__device__ float g_psum[NB * NCHUNK];
__device__ float g_psq [NB * NCHUNK];
__device__ __align__(16) float g_ktr[LEN*NH];   // [l][n] transposed real kernel
__device__ __align__(16) float g_kti[LEN*NH];   // [l][n] transposed imag kernel

// ---------------------------------------------------------------------------
// Pass A1: partial sums, grid (NB, NCHUNK) -> full-chip coverage
// ---------------------------------------------------------------------------
__global__ void __launch_bounds__(256)
stats_partial(const float* __restrict__ x, int S) {
    const int b = blockIdx.x, c = blockIdx.y;
    const int chunk = (S + NCHUNK - 1) / NCHUNK;
    const int s0 = c * chunk;
    const int s1 = min(s0 + chunk, S);
    const float* xb = x + (size_t)b * S + s0;
    const int n = s1 - s0;

    float sum = 0.f, sq = 0.f;
    // scalar prologue to 16B alignment
    int pre = (int)(((16u - (unsigned)((size_t)xb & 15u)) & 15u) >> 2);
    if (pre > n) pre = n;
    for (int i = threadIdx.x; i < pre; i += 256) {
        float v = xb[i]; sum += v; sq += v*v;
    }
    int n4 = (n - pre) >> 2;
    const float4* x4 = (const float4*)(xb + pre);
    for (int i = threadIdx.x; i < n4; i += 256) {
        float4 v = x4[i];
        sum += v.x + v.y + v.z + v.w;
        sq  += v.x*v.x + v.y*v.y + v.z*v.z + v.w*v.w;
    }
    for (int i = pre + (n4 << 2) + threadIdx.x; i < n; i += 256) {
        float v = xb[i]; sum += v; sq += v*v;
    }

    __shared__ float ssum[8], ssq[8];
    #pragma unroll
    for (int o = 16; o > 0; o >>= 1) {
        sum += __shfl_xor_sync(~0u, sum, o);
        sq  += __shfl_xor_sync(~0u, sq,  o);
    }
    int w = threadIdx.x >> 5, ln = threadIdx.x & 31;
    if (ln == 0) { ssum[w] = sum; ssq[w] = sq; }
    __syncthreads();
    if (w == 0 && ln < 8) {
        sum = ssum[ln]; sq = ssq[ln];
        #pragma unroll
        for (int o = 4; o > 0; o >>= 1) {
            sum += __shfl_xor_sync(0xffu, sum, o);
            sq  += __shfl_xor_sync(0xffu, sq,  o);
        }
        if (ln == 0) {
            g_psum[b * NCHUNK + c] = sum;
            g_psq [b * NCHUNK + c] = sq;
        }
    }
}

// Pass A2: finalize mu/sd per batch
__global__ void stats_final(int S) {
    int b = threadIdx.x;
    if (b >= NB) return;
    float sum = 0.f, sq = 0.f;
    #pragma unroll
    for (int c = 0; c < NCHUNK; c++) {
        sum += g_psum[b * NCHUNK + c];
        sq  += g_psq [b * NCHUNK + c];
    }
    float mu  = sum / (float)S;
    float var = sq / (float)S - mu * mu;
    g_mu[b] = mu;
    g_sd[b] = sqrtf(fmaxf(var, 0.f));
}

// ---------------------------------------------------------------------------
// One-time kernel transpose: [n][l] -> [l][n], n < 128 only
// ---------------------------------------------------------------------------
__global__ void transpose_kernel(const float* __restrict__ kr,
                                 const float* __restrict__ ki) {
    int idx = blockIdx.x * blockDim.x + threadIdx.x;
    if (idx >= LEN * NH) return;
    int n = idx % NH, l = idx / NH;        // write coalesced in n
    g_ktr[idx] = kr[n * LEN + l];
    g_kti[idx] = ki[n * LEN + l];
}

// ---------------------------------------------------------------------------
// Pass B: fused frame + DFT(128 bins) + mag + log10 + per-t bin-normalize
// grid = (T/TT, B), 256 threads.
// Packed-FFMA2 register tile: 2 n-pairs x 8 t per thread (re+im).
//   tn = tid&31  -> n = tn*4 + {0,1 | 2,3}  (pairs packed in 64-bit regs)
//   g  = tid>>5  -> t = g*8 + j             (each warp owns 8 complete t's)
// ---------------------------------------------------------------------------
__global__ void __launch_bounds__(256, 2)
dft_kernel(const float* __restrict__ x, float* __restrict__ out, int S, int T) {
    __shared__ __align__(16) float s_sig[SIGTILE + 14];  // 9664; reused as vals[t][132]
    __shared__ __align__(16) float s_kr[KC * NH];
    __shared__ __align__(16) float s_ki[KC * NH];

    const int b   = blockIdx.y;
    const int t0  = blockIdx.x * TT;
    const int tid = threadIdx.x;

    const float mu  = g_mu[b];
    const float inv = 1.f / (g_sd[b] + EPSF);

    const float* base = x + (size_t)b * S + (size_t)t0 * SHIFT;
    for (int i = tid; i < SIGTILE; i += 256)
        s_sig[i] = (base[i] - mu) * inv;
    __syncthreads();

    const int tn = tid & 31;
    const int g  = tid >> 5;

    ull aR[2][8], aI[2][8];
    #pragma unroll
    for (int i = 0; i < 2; i++)
        #pragma unroll
        for (int j = 0; j < 8; j++) { aR[i][j] = 0ull; aI[i][j] = 0ull; }

    for (int lc = 0; lc < LEN; lc += KC) {
        ((float4*)s_kr)[tid] = ((const float4*)(g_ktr + lc * NH))[tid];
        ((float4*)s_ki)[tid] = ((const float4*)(g_kti + lc * NH))[tid];
        __syncthreads();
        #pragma unroll
        for (int l = 0; l < KC; l++) {
            const ulonglong2 kr2 = *(const ulonglong2*)&s_kr[l * NH + tn * 4];
            const ulonglong2 ki2 = *(const ulonglong2*)&s_ki[l * NH + tn * 4];
            const int ls = lc + l;
            #pragma unroll
            for (int j = 0; j < 8; j++) {
                const ull s2 = dup2(s_sig[SHIFT * (g * 8 + j) + ls]);  // (s,s)
                ffma2(aR[0][j], kr2.x, s2);
                ffma2(aR[1][j], kr2.y, s2);
                ffma2(aI[0][j], ki2.x, s2);
                ffma2(aI[1][j], ki2.y, s2);
            }
        }
        __syncthreads();
    }

    // epilogue: mag -> log10 -> normalize over the 128 bins of each t
    float* vals = s_sig;   // reuse as [t][132] (padded vs bank conflicts)
    #pragma unroll
    for (int j = 0; j < 8; j++) {
        const int tl = g * 8 + j;
        const float2 r0 = unpack2(aR[0][j]), r1 = unpack2(aR[1][j]);
        const float2 i0 = unpack2(aI[0][j]), i1 = unpack2(aI[1][j]);
        float v[4];
        v[0] = logf(fmaxf(sqrtf(r0.x*r0.x + i0.x*i0.x), EPSF)) * INV_LN10;
        v[1] = logf(fmaxf(sqrtf(r0.y*r0.y + i0.y*i0.y), EPSF)) * INV_LN10;
        v[2] = logf(fmaxf(sqrtf(r1.x*r1.x + i1.x*i1.x), EPSF)) * INV_LN10;
        v[3] = logf(fmaxf(sqrtf(r1.y*r1.y + i1.y*i1.y), EPSF)) * INV_LN10;

        float p = v[0] + v[1] + v[2] + v[3];
        float q = v[0]*v[0] + v[1]*v[1] + v[2]*v[2] + v[3]*v[3];
        #pragma unroll
        for (int o = 16; o > 0; o >>= 1) {
            p += __shfl_xor_sync(~0u, p, o);
            q += __shfl_xor_sync(~0u, q, o);
        }
        const float mean = p * (1.f / NH);
        const float var  = q * (1.f / NH) - mean * mean;
        const float invn = 1.f / (sqrtf(fmaxf(var, 0.f)) + EPSF);
        float4 w = make_float4((v[0] - mean) * invn, (v[1] - mean) * invn,
                               (v[2] - mean) * invn, (v[3] - mean) * invn);
        *(float4*)&vals[tl * 132 + tn * 4] = w;
    }
    __syncthreads();

    // coalesced store: out[b][n][t0 + tc]
    for (int k = tid; k < NH * TT; k += 256) {
        const int n  = k >> 6;
        const int tc = k & 63;
        out[((size_t)(b * NH + n)) * T + t0 + tc] = vals[tc * 132 + n];
    }
}

// ---------------------------------------------------------------------------
extern "C" void kernel_launch(void* const* d_in, const int* in_sizes, int n_in,
                              void* d_out, int out_size) {
    const float* x  = (const float*)d_in[0];
    const float* kr = (const float*)d_in[1];
    const float* ki = (const float*)d_in[2];
    float* out = (float*)d_out;

    const int S = in_sizes[0] / NB;            // 480050
    const int T = (S - LEN) / SHIFT + 1;       // 3200

    stats_partial<<<dim3(NB, NCHUNK), 256>>>(x, S);
    stats_final<<<1, 64>>>(S);
    transpose_kernel<<<(LEN * NH + 255) / 256, 256>>>(kr, ki);
    dft_kernel<<<dim3(T / TT, NB), 256>>>(x, out, S, T);
}

// round 7
// speedup vs baseline: 2.0318x; 1.9007x over previous
#include <cuda_runtime.h>
#include <cuda_fp16.h>
#include <math.h>
#include <stdint.h>

#define NB     64
#define SHIFT  150
#define LEN    200
#define NH     128
#define MTILE  128
#define NCHUNK 8
#define EPSF   1e-7f
#define HALF_INV_LN10 0.21714724095162588f

#define FP     200                  // frame pitch (halfs)
#define BP     120                  // B pitch (halfs)
#define KC0    112                  // chunk 0: 7 k16-steps
#define KC1    96                   // chunk 1: 6 k16-steps (zero-padded >=200)

// smem layout (bytes)
#define SM_FH   0                   // frames hi [128][200] half = 51200
#define SM_FL   51200               // frames lo
#define SM_BH   102400              // B chunk hi [256][120] half = 61440
#define SM_BL   163840              // B chunk lo
#define SMEM_TOTAL 225280

// epilogue overlay
#define OFF_V    0
#define OFF_IM   67584
#define OFF_MEAN 135168
#define OFF_INV  135680

__device__ float g_mu[NB];
__device__ float g_sd[NB];
__device__ float g_psum[NB * NCHUNK];
__device__ float g_psq [NB * NCHUNK];
// prepped B: [chunk][256][BP] halfs, hi and lo
__device__ __align__(16) __half g_bh[2 * 256 * BP];
__device__ __align__(16) __half g_bl[2 * 256 * BP];

__device__ __forceinline__ void mma16(float* d, const uint32_t* a, const uint32_t* bf) {
    asm volatile("mma.sync.aligned.m16n8k16.row.col.f32.f16.f16.f32 "
        "{%0,%1,%2,%3}, {%4,%5,%6,%7}, {%8,%9}, {%0,%1,%2,%3};"
        : "+f"(d[0]), "+f"(d[1]), "+f"(d[2]), "+f"(d[3])
        : "r"(a[0]), "r"(a[1]), "r"(a[2]), "r"(a[3]), "r"(bf[0]), "r"(bf[1]));
}

// ---------------------------------------------------------------------------
__global__ void __launch_bounds__(256)
stats_partial(const float* __restrict__ x, int S) {
    const int b = blockIdx.x, c = blockIdx.y;
    const int chunk = (S + NCHUNK - 1) / NCHUNK;
    const int s0 = c * chunk;
    const int s1 = min(s0 + chunk, S);
    const float* xb = x + (size_t)b * S + s0;
    const int n = s1 - s0;

    float sum = 0.f, sq = 0.f;
    int pre = (int)(((16u - (unsigned)((size_t)xb & 15u)) & 15u) >> 2);
    if (pre > n) pre = n;
    for (int i = threadIdx.x; i < pre; i += 256) { float v = xb[i]; sum += v; sq += v*v; }
    int n4 = (n - pre) >> 2;
    const float4* x4 = (const float4*)(xb + pre);
    for (int i = threadIdx.x; i < n4; i += 256) {
        float4 v = x4[i];
        sum += v.x + v.y + v.z + v.w;
        sq  += v.x*v.x + v.y*v.y + v.z*v.z + v.w*v.w;
    }
    for (int i = pre + (n4 << 2) + threadIdx.x; i < n; i += 256) { float v = xb[i]; sum += v; sq += v*v; }

    __shared__ float ssum[8], ssq[8];
    #pragma unroll
    for (int o = 16; o > 0; o >>= 1) {
        sum += __shfl_xor_sync(~0u, sum, o);
        sq  += __shfl_xor_sync(~0u, sq,  o);
    }
    int w = threadIdx.x >> 5, ln = threadIdx.x & 31;
    if (ln == 0) { ssum[w] = sum; ssq[w] = sq; }
    __syncthreads();
    if (w == 0 && ln < 8) {
        sum = ssum[ln]; sq = ssq[ln];
        #pragma unroll
        for (int o = 4; o > 0; o >>= 1) {
            sum += __shfl_xor_sync(0xffu, sum, o);
            sq  += __shfl_xor_sync(0xffu, sq,  o);
        }
        if (ln == 0) { g_psum[b*NCHUNK+c] = sum; g_psq[b*NCHUNK+c] = sq; }
    }
}

__global__ void stats_final(int S) {
    int b = threadIdx.x;
    if (b >= NB) return;
    float sum = 0.f, sq = 0.f;
    #pragma unroll
    for (int c = 0; c < NCHUNK; c++) { sum += g_psum[b*NCHUNK+c]; sq += g_psq[b*NCHUNK+c]; }
    float mu  = sum / (float)S;
    float var = sq / (float)S - mu * mu;
    g_mu[b] = mu;
    g_sd[b] = sqrtf(fmaxf(var, 0.f));
}

// ---------------------------------------------------------------------------
// Prep: split DFT kernels into fp16 hi/lo, chunk-pitched layout.
// ---------------------------------------------------------------------------
__global__ void prep_b_kernel(const float* __restrict__ kr,
                              const float* __restrict__ ki) {
    int idx = blockIdx.x * blockDim.x + threadIdx.x;
    if (idx >= 2 * 256 * BP) return;
    int kk = idx % BP;
    int n  = (idx / BP) & 255;
    int c  = idx / (256 * BP);
    int k  = c * KC0 + kk;
    int kc = c ? KC1 : KC0;
    float v = 0.f;
    if (kk < kc && k < LEN)
        v = ((n < NH) ? kr : ki)[(size_t)(n & 127) * LEN + k];
    __half h = __float2half_rn(v);
    g_bh[idx] = h;
    g_bl[idx] = __float2half_rn(v - __half2float(h));
}

// ---------------------------------------------------------------------------
// Fused: frame+normalize (fp16 hi/lo) + 3xFP16 HMMA DFT + mag/log10 + bin-norm
// grid (T/128, NB), 512 threads = 16 warps (4m x 4n); warp tile 32t x 64n.
// ---------------------------------------------------------------------------
__global__ void __launch_bounds__(512, 1)
dft_mma_kernel(const float* __restrict__ x,
               float* __restrict__ out, int S, int T) {
    extern __shared__ char smem[];

    const int tid  = threadIdx.x;
    const int lane = tid & 31;
    const int wid  = tid >> 5;
    const int g    = lane >> 2;
    const int q    = lane & 3;
    const int wm   = wid & 3;
    const int wn   = wid >> 2;
    const int tw   = wm * 32;
    const int nw   = wn * 64;

    const int b  = blockIdx.y;
    const int t0 = blockIdx.x * MTILE;
    const float mu  = g_mu[b];
    const float inv = 1.f / (g_sd[b] + EPSF);
    const float* xrow = x + (size_t)b * S + (size_t)t0 * SHIFT;

    // stage frames: [t][k] normalized, split hi/lo (pairs of k -> one b32)
    {
        uint32_t* fh = (uint32_t*)(smem + SM_FH);
        uint32_t* fl = (uint32_t*)(smem + SM_FL);
        for (int i = tid; i < MTILE * (FP / 2); i += 512) {
            const int t  = i / (FP / 2);
            const int kp = (i % (FP / 2)) * 2;
            const float* src = xrow + t * SHIFT + kp;
            float v0 = (src[0] - mu) * inv;
            float v1 = (src[1] - mu) * inv;
            __half h0 = __float2half_rn(v0), h1 = __float2half_rn(v1);
            __half l0 = __float2half_rn(v0 - __half2float(h0));
            __half l1 = __float2half_rn(v1 - __half2float(h1));
            fh[i] = (uint32_t)__half_as_ushort(h0) | ((uint32_t)__half_as_ushort(h1) << 16);
            fl[i] = (uint32_t)__half_as_ushort(l0) | ((uint32_t)__half_as_ushort(l1) << 16);
        }
    }

    float acc[2][8][4];
    #pragma unroll
    for (int mt = 0; mt < 2; mt++)
        #pragma unroll
        for (int nt = 0; nt < 8; nt++)
            #pragma unroll
            for (int i = 0; i < 4; i++) acc[mt][nt][i] = 0.f;

    const uint32_t* fh = (const uint32_t*)(smem + SM_FH);
    const uint32_t* fl = (const uint32_t*)(smem + SM_FL);

    #pragma unroll
    for (int c = 0; c < 2; c++) {
        // stage B chunk (raw copies of prepped fp16)
        {
            const uint4* sbh = (const uint4*)(g_bh + c * 256 * BP);
            const uint4* sbl = (const uint4*)(g_bl + c * 256 * BP);
            uint4* dbh = (uint4*)(smem + SM_BH);
            uint4* dbl = (uint4*)(smem + SM_BL);
            for (int i = tid; i < 256 * BP / 8; i += 512) {
                dbh[i] = sbh[i];
                dbl[i] = sbl[i];
            }
        }
        __syncthreads();

        const uint32_t* bh = (const uint32_t*)(smem + SM_BH);
        const uint32_t* bl = (const uint32_t*)(smem + SM_BL);
        const int nsteps = c ? (KC1 / 16) : (KC0 / 16);

        #pragma unroll
        for (int ks = 0; ks < 7; ks++) {
            if (ks >= nsteps) break;
            const int kb = c * KC0 + ks * 16;       // global k of step
            const int kw = (ks * 16 + 2 * q) >> 1;  // word offset in B chunk

            uint32_t ah[2][4], al[2][4];
            #pragma unroll
            for (int mt = 0; mt < 2; mt++) {
                const int base = (tw + mt * 16 + g) * (FP / 2) + ((kb + 2 * q) >> 1);
                ah[mt][0] = fh[base];
                ah[mt][1] = fh[base + 8 * (FP / 2)];      // row g+8  (FIXED: was 4 rows)
                ah[mt][2] = fh[base + 4];                 // k+8
                ah[mt][3] = fh[base + 8 * (FP / 2) + 4];  // row g+8, k+8 (FIXED)
                al[mt][0] = fl[base];
                al[mt][1] = fl[base + 8 * (FP / 2)];      // FIXED
                al[mt][2] = fl[base + 4];
                al[mt][3] = fl[base + 8 * (FP / 2) + 4];  // FIXED
            }
            #pragma unroll
            for (int nt = 0; nt < 8; nt++) {
                const int baddr = (nw + nt * 8 + g) * (BP / 2) + kw;
                uint32_t bhf[2], blf[2];
                bhf[0] = bh[baddr];     bhf[1] = bh[baddr + 4];
                blf[0] = bl[baddr];     blf[1] = bl[baddr + 4];
                mma16(acc[0][nt], ah[0], bhf);
                mma16(acc[1][nt], ah[1], bhf);
                mma16(acc[0][nt], al[0], bhf);
                mma16(acc[1][nt], al[1], bhf);
                mma16(acc[0][nt], ah[0], blf);
                mma16(acc[1][nt], ah[1], blf);
            }
        }
        __syncthreads();
    }

    // ---- epilogue ----
    float* imst = (float*)(smem + OFF_IM);
    float* vst  = (float*)(smem + OFF_V);
    float* mn   = (float*)(smem + OFF_MEAN);
    float* ivn  = (float*)(smem + OFF_INV);

    if (wn >= 2) {   // stage imaginary part (cols 128..255)
        #pragma unroll
        for (int mt = 0; mt < 2; mt++)
            #pragma unroll
            for (int nt = 0; nt < 8; nt++) {
                const int ni = (wn - 2) * 64 + nt * 8 + 2 * q;
                const int t  = tw + mt * 16 + g;
                imst[ni * 132 + t]           = acc[mt][nt][0];
                imst[(ni + 1) * 132 + t]     = acc[mt][nt][1];
                imst[ni * 132 + t + 8]       = acc[mt][nt][2];
                imst[(ni + 1) * 132 + t + 8] = acc[mt][nt][3];
            }
    }
    __syncthreads();
    if (wn < 2) {    // combine with real part -> v = log10(mag)
        #pragma unroll
        for (int mt = 0; mt < 2; mt++)
            #pragma unroll
            for (int nt = 0; nt < 8; nt++) {
                const int n = nw + nt * 8 + 2 * q;
                const int t = tw + mt * 16 + g;
                #pragma unroll
                for (int e = 0; e < 4; e++) {
                    const int nn = n + (e & 1);
                    const int tt = t + ((e >> 1) << 3);
                    float re = acc[mt][nt][e];
                    float im = imst[nn * 132 + tt];
                    float m2 = fmaxf(re * re + im * im, 1e-14f);
                    vst[nn * 132 + tt] = __logf(m2) * HALF_INV_LN10;
                }
            }
    }
    __syncthreads();
    if (tid < MTILE) {
        const int t = tid;
        float sum = 0.f, sq = 0.f;
        #pragma unroll 8
        for (int n = 0; n < NH; n++) {
            float v = vst[n * 132 + t];
            sum += v; sq += v * v;
        }
        const float mean = sum * (1.f / NH);
        const float var  = sq * (1.f / NH) - mean * mean;
        mn[t]  = mean;
        ivn[t] = 1.f / (sqrtf(fmaxf(var, 0.f)) + EPSF);
    }
    __syncthreads();
    for (int idx = tid; idx < NH * MTILE; idx += 512) {
        const int n = idx >> 7, t = idx & 127;
        out[((size_t)(b * NH + n)) * T + t0 + t] = (vst[n * 132 + t] - mn[t]) * ivn[t];
    }
}

// ---------------------------------------------------------------------------
extern "C" void kernel_launch(void* const* d_in, const int* in_sizes, int n_in,
                              void* d_out, int out_size) {
    const float* x  = (const float*)d_in[0];
    const float* kr = (const float*)d_in[1];
    const float* ki = (const float*)d_in[2];
    float* out = (float*)d_out;

    const int S = in_sizes[0] / NB;            // 480050
    const int T = (S - LEN) / SHIFT + 1;       // 3200

    cudaFuncSetAttribute(dft_mma_kernel, cudaFuncAttributeMaxDynamicSharedMemorySize, SMEM_TOTAL);

    stats_partial<<<dim3(NB, NCHUNK), 256>>>(x, S);
    stats_final<<<1, 64>>>(S);
    prep_b_kernel<<<(2 * 256 * BP + 255) / 256, 256>>>(kr, ki);
    dft_mma_kernel<<<dim3(T / MTILE, NB), 512, SMEM_TOTAL>>>(x, out, S, T);
}

// round 8
// speedup vs baseline: 2.0611x; 1.0145x over previous
#include <cuda_runtime.h>
#include <cuda_fp16.h>
#include <math.h>
#include <stdint.h>

#define NB     64
#define SHIFT  150
#define LEN    200
#define NH     128
#define MTILE  64                   // t rows per block
#define NCHUNK 8
#define EPSF   1e-7f
#define HALF_INV_LN10 0.21714724095162588f

#define FP     200                  // frame pitch (halfs); 100 words -> banks 4g+q
#define BP     56                   // B pitch (halfs); 28 words -> banks 28g+q (conflict-free)
#define KC     48                   // K per chunk (3 k16 steps); chunks: 48*4 + 16 = 208
#define NCHK   5

// per-CTA smem layout (bytes)
#define SM_FH   0                   // frames hi [64][200] half = 25600
#define SM_FL   25600               // frames lo
#define SM_BH   51200               // B chunk hi [256][56] half = 28672
#define SM_BL   79872               // B chunk lo
#define SMEM_TOTAL 108544

// epilogue overlay (pitch 68 floats)
#define OFF_V    0                  // [128][68] f32 = 34816
#define OFF_IM   34816
#define OFF_MEAN 69632              // 128 f32
#define OFF_INV  70144

__device__ float g_mu[NB];
__device__ float g_sd[NB];
__device__ float g_psum[NB * NCHUNK];
__device__ float g_psq [NB * NCHUNK];
// prepped B: [chunk 0..4][256][BP] halfs, hi and lo
__device__ __align__(16) __half g_bh[NCHK * 256 * BP];
__device__ __align__(16) __half g_bl[NCHK * 256 * BP];

__device__ __forceinline__ void mma16(float* d, const uint32_t* a, const uint32_t* bf) {
    asm volatile("mma.sync.aligned.m16n8k16.row.col.f32.f16.f16.f32 "
        "{%0,%1,%2,%3}, {%4,%5,%6,%7}, {%8,%9}, {%0,%1,%2,%3};"
        : "+f"(d[0]), "+f"(d[1]), "+f"(d[2]), "+f"(d[3])
        : "r"(a[0]), "r"(a[1]), "r"(a[2]), "r"(a[3]), "r"(bf[0]), "r"(bf[1]));
}

// ---------------------------------------------------------------------------
__global__ void __launch_bounds__(256)
stats_partial(const float* __restrict__ x, int S) {
    const int b = blockIdx.x, c = blockIdx.y;
    const int chunk = (S + NCHUNK - 1) / NCHUNK;
    const int s0 = c * chunk;
    const int s1 = min(s0 + chunk, S);
    const float* xb = x + (size_t)b * S + s0;
    const int n = s1 - s0;

    float sum = 0.f, sq = 0.f;
    int pre = (int)(((16u - (unsigned)((size_t)xb & 15u)) & 15u) >> 2);
    if (pre > n) pre = n;
    for (int i = threadIdx.x; i < pre; i += 256) { float v = xb[i]; sum += v; sq += v*v; }
    int n4 = (n - pre) >> 2;
    const float4* x4 = (const float4*)(xb + pre);
    for (int i = threadIdx.x; i < n4; i += 256) {
        float4 v = x4[i];
        sum += v.x + v.y + v.z + v.w;
        sq  += v.x*v.x + v.y*v.y + v.z*v.z + v.w*v.w;
    }
    for (int i = pre + (n4 << 2) + threadIdx.x; i < n; i += 256) { float v = xb[i]; sum += v; sq += v*v; }

    __shared__ float ssum[8], ssq[8];
    #pragma unroll
    for (int o = 16; o > 0; o >>= 1) {
        sum += __shfl_xor_sync(~0u, sum, o);
        sq  += __shfl_xor_sync(~0u, sq,  o);
    }
    int w = threadIdx.x >> 5, ln = threadIdx.x & 31;
    if (ln == 0) { ssum[w] = sum; ssq[w] = sq; }
    __syncthreads();
    if (w == 0 && ln < 8) {
        sum = ssum[ln]; sq = ssq[ln];
        #pragma unroll
        for (int o = 4; o > 0; o >>= 1) {
            sum += __shfl_xor_sync(0xffu, sum, o);
            sq  += __shfl_xor_sync(0xffu, sq,  o);
        }
        if (ln == 0) { g_psum[b*NCHUNK+c] = sum; g_psq[b*NCHUNK+c] = sq; }
    }
}

__global__ void stats_final(int S) {
    int b = threadIdx.x;
    if (b >= NB) return;
    float sum = 0.f, sq = 0.f;
    #pragma unroll
    for (int c = 0; c < NCHUNK; c++) { sum += g_psum[b*NCHUNK+c]; sq += g_psq[b*NCHUNK+c]; }
    float mu  = sum / (float)S;
    float var = sq / (float)S - mu * mu;
    g_mu[b] = mu;
    g_sd[b] = sqrtf(fmaxf(var, 0.f));
}

// ---------------------------------------------------------------------------
// Prep: split DFT kernels into fp16 hi/lo, chunk-pitched layout.
// ---------------------------------------------------------------------------
__global__ void prep_b_kernel(const float* __restrict__ kr,
                              const float* __restrict__ ki) {
    int idx = blockIdx.x * blockDim.x + threadIdx.x;
    if (idx >= NCHK * 256 * BP) return;
    int kk = idx % BP;
    int n  = (idx / BP) & 255;
    int c  = idx / (256 * BP);
    int k  = c * KC + kk;
    float v = 0.f;
    if (kk < KC && k < LEN)
        v = ((n < NH) ? kr : ki)[(size_t)(n & 127) * LEN + k];
    __half h = __float2half_rn(v);
    g_bh[idx] = h;
    g_bl[idx] = __float2half_rn(v - __half2float(h));
}

// ---------------------------------------------------------------------------
// Fused: frame+normalize (fp16 hi/lo) + 3xFP16 HMMA DFT + mag/log10 + bin-norm
// grid (T/64, NB), 256 threads = 8 warps (2m x 4n); warp tile 32t x 64n.
// 2 CTAs/SM: staging/epilogue of one overlaps MMA of the other.
// ---------------------------------------------------------------------------
__global__ void __launch_bounds__(256, 2)
dft_mma_kernel(const float* __restrict__ x,
               float* __restrict__ out, int S, int T) {
    extern __shared__ char smem[];

    const int tid  = threadIdx.x;
    const int lane = tid & 31;
    const int wid  = tid >> 5;
    const int g    = lane >> 2;
    const int q    = lane & 3;
    const int wm   = wid & 1;
    const int wn   = wid >> 1;
    const int tw   = wm * 32;
    const int nw   = wn * 64;

    const int b  = blockIdx.y;
    const int t0 = blockIdx.x * MTILE;
    const float mu  = g_mu[b];
    const float inv = 1.f / (g_sd[b] + EPSF);
    const float* xrow = x + (size_t)b * S + (size_t)t0 * SHIFT;

    // stage frames: [t][k] normalized, split hi/lo (pairs of k -> one b32)
    {
        uint32_t* fh = (uint32_t*)(smem + SM_FH);
        uint32_t* fl = (uint32_t*)(smem + SM_FL);
        for (int i = tid; i < MTILE * (FP / 2); i += 256) {
            const int t  = i / (FP / 2);
            const int kp = (i % (FP / 2)) * 2;
            const float* src = xrow + t * SHIFT + kp;
            float v0 = (src[0] - mu) * inv;
            float v1 = (src[1] - mu) * inv;
            __half h0 = __float2half_rn(v0), h1 = __float2half_rn(v1);
            __half l0 = __float2half_rn(v0 - __half2float(h0));
            __half l1 = __float2half_rn(v1 - __half2float(h1));
            fh[i] = (uint32_t)__half_as_ushort(h0) | ((uint32_t)__half_as_ushort(h1) << 16);
            fl[i] = (uint32_t)__half_as_ushort(l0) | ((uint32_t)__half_as_ushort(l1) << 16);
        }
    }

    float acc[2][8][4];
    #pragma unroll
    for (int mt = 0; mt < 2; mt++)
        #pragma unroll
        for (int nt = 0; nt < 8; nt++)
            #pragma unroll
            for (int i = 0; i < 4; i++) acc[mt][nt][i] = 0.f;

    const uint32_t* fh = (const uint32_t*)(smem + SM_FH);
    const uint32_t* fl = (const uint32_t*)(smem + SM_FL);

    for (int c = 0; c < NCHK; c++) {
        // stage B chunk (raw copies of prepped fp16)
        {
            const uint4* sbh = (const uint4*)(g_bh + c * 256 * BP);
            const uint4* sbl = (const uint4*)(g_bl + c * 256 * BP);
            uint4* dbh = (uint4*)(smem + SM_BH);
            uint4* dbl = (uint4*)(smem + SM_BL);
            #pragma unroll
            for (int i = 0; i < 7; i++) {
                dbh[tid + i * 256] = sbh[tid + i * 256];
                dbl[tid + i * 256] = sbl[tid + i * 256];
            }
        }
        __syncthreads();

        const uint32_t* bh = (const uint32_t*)(smem + SM_BH);
        const uint32_t* bl = (const uint32_t*)(smem + SM_BL);
        const int nsteps = (c < 4) ? 3 : 1;

        #pragma unroll
        for (int ks = 0; ks < 3; ks++) {
            if (ks >= nsteps) break;
            const int kg = c * KC + ks * 16;        // global k of step
            const int kw = ks * 8 + q;              // word offset in B chunk

            uint32_t ah[2][4], al[2][4];
            #pragma unroll
            for (int mt = 0; mt < 2; mt++) {
                const int base = (tw + mt * 16 + g) * (FP / 2) + (kg >> 1) + q;
                ah[mt][0] = fh[base];
                ah[mt][1] = fh[base + 8 * (FP / 2)];
                ah[mt][2] = fh[base + 4];
                ah[mt][3] = fh[base + 8 * (FP / 2) + 4];
                al[mt][0] = fl[base];
                al[mt][1] = fl[base + 8 * (FP / 2)];
                al[mt][2] = fl[base + 4];
                al[mt][3] = fl[base + 8 * (FP / 2) + 4];
            }
            // term-major over nt-halves: RAW reuse distance = 8 MMAs
            #pragma unroll
            for (int h = 0; h < 2; h++) {
                uint32_t bhf[4][2], blf[4][2];
                #pragma unroll
                for (int u = 0; u < 4; u++) {
                    const int nt = h * 4 + u;
                    const int baddr = (nw + nt * 8 + g) * (BP / 2) + kw;
                    bhf[u][0] = bh[baddr];  bhf[u][1] = bh[baddr + 4];
                    blf[u][0] = bl[baddr];  blf[u][1] = bl[baddr + 4];
                }
                #pragma unroll
                for (int u = 0; u < 4; u++) {
                    mma16(acc[0][h * 4 + u], ah[0], bhf[u]);
                    mma16(acc[1][h * 4 + u], ah[1], bhf[u]);
                }
                #pragma unroll
                for (int u = 0; u < 4; u++) {
                    mma16(acc[0][h * 4 + u], al[0], bhf[u]);
                    mma16(acc[1][h * 4 + u], al[1], bhf[u]);
                }
                #pragma unroll
                for (int u = 0; u < 4; u++) {
                    mma16(acc[0][h * 4 + u], ah[0], blf[u]);
                    mma16(acc[1][h * 4 + u], ah[1], blf[u]);
                }
            }
        }
        __syncthreads();
    }

    // ---- epilogue (pitch 68) ----
    float* imst = (float*)(smem + OFF_IM);
    float* vst  = (float*)(smem + OFF_V);
    float* mn   = (float*)(smem + OFF_MEAN);
    float* ivn  = (float*)(smem + OFF_INV);

    if (wn >= 2) {   // stage imaginary part (cols 128..255)
        #pragma unroll
        for (int mt = 0; mt < 2; mt++)
            #pragma unroll
            for (int nt = 0; nt < 8; nt++) {
                const int ni = (wn - 2) * 64 + nt * 8 + 2 * q;
                const int t  = tw + mt * 16 + g;
                imst[ni * 68 + t]           = acc[mt][nt][0];
                imst[(ni + 1) * 68 + t]     = acc[mt][nt][1];
                imst[ni * 68 + t + 8]       = acc[mt][nt][2];
                imst[(ni + 1) * 68 + t + 8] = acc[mt][nt][3];
            }
    }
    __syncthreads();
    if (wn < 2) {    // combine with real part -> v = log10(mag)
        #pragma unroll
        for (int mt = 0; mt < 2; mt++)
            #pragma unroll
            for (int nt = 0; nt < 8; nt++) {
                const int n = nw + nt * 8 + 2 * q;
                const int t = tw + mt * 16 + g;
                #pragma unroll
                for (int e = 0; e < 4; e++) {
                    const int nn = n + (e & 1);
                    const int tt = t + ((e >> 1) << 3);
                    float re = acc[mt][nt][e];
                    float im = imst[nn * 68 + tt];
                    float m2 = fmaxf(re * re + im * im, 1e-14f);
                    vst[nn * 68 + tt] = __logf(m2) * HALF_INV_LN10;
                }
            }
    }
    __syncthreads();
    if (tid < MTILE) {
        const int t = tid;
        float sum = 0.f, sq = 0.f;
        #pragma unroll 8
        for (int n = 0; n < NH; n++) {
            float v = vst[n * 68 + t];
            sum += v; sq += v * v;
        }
        const float mean = sum * (1.f / NH);
        const float var  = sq * (1.f / NH) - mean * mean;
        mn[t]  = mean;
        ivn[t] = 1.f / (sqrtf(fmaxf(var, 0.f)) + EPSF);
    }
    __syncthreads();
    for (int idx = tid; idx < NH * MTILE; idx += 256) {
        const int n = idx >> 6, t = idx & 63;
        out[((size_t)(b * NH + n)) * T + t0 + t] = (vst[n * 68 + t] - mn[t]) * ivn[t];
    }
}

// ---------------------------------------------------------------------------
extern "C" void kernel_launch(void* const* d_in, const int* in_sizes, int n_in,
                              void* d_out, int out_size) {
    const float* x  = (const float*)d_in[0];
    const float* kr = (const float*)d_in[1];
    const float* ki = (const float*)d_in[2];
    float* out = (float*)d_out;

    const int S = in_sizes[0] / NB;            // 480050
    const int T = (S - LEN) / SHIFT + 1;       // 3200

    cudaFuncSetAttribute(dft_mma_kernel, cudaFuncAttributeMaxDynamicSharedMemorySize, SMEM_TOTAL);

    stats_partial<<<dim3(NB, NCHUNK), 256>>>(x, S);
    stats_final<<<1, 64>>>(S);
    prep_b_kernel<<<(NCHK * 256 * BP + 255) / 256, 256>>>(kr, ki);
    dft_mma_kernel<<<dim3(T / MTILE, NB), 256, SMEM_TOTAL>>>(x, out, S, T);
}

// round 9
// speedup vs baseline: 2.1497x; 1.0430x over previous
#include <cuda_runtime.h>
#include <cuda_fp16.h>
#include <math.h>
#include <stdint.h>

#define NB     64
#define SHIFT  150
#define LEN    200
#define NH     128
#define MTILE  64
#define NCHUNK 8
#define EPSF   1e-7f
#define HALF_INV_LN10 0.21714724095162588f

#define FP     200                  // frame pitch (halfs); rows -> banks 4r mod 32
#define BP     56                   // B pitch (halfs); rows -> banks 28r mod 32
#define KC     48                   // K per chunk (3 k16 steps); 48*4 + 16 = 208
#define NCHK   5

// per-CTA smem layout (bytes)
#define SM_FH   0                   // frames hi [64][200] half = 25600
#define SM_FL   25600
#define SM_BH   51200               // B chunk hi [256][56] half = 28672
#define SM_BL   79872
#define SMEM_TOTAL 108544

// epilogue overlay (pitch 68 floats)
#define OFF_V    0
#define OFF_IM   34816
#define OFF_MEAN 69632
#define OFF_INV  70144

__device__ float g_mu[NB];
__device__ float g_sd[NB];
__device__ float g_psum[NB * NCHUNK];
__device__ float g_psq [NB * NCHUNK];
__device__ __align__(16) __half g_bh[NCHK * 256 * BP];
__device__ __align__(16) __half g_bl[NCHK * 256 * BP];

__device__ __forceinline__ void mma16(float* d, const uint32_t* a, const uint32_t* bf) {
    asm volatile("mma.sync.aligned.m16n8k16.row.col.f32.f16.f16.f32 "
        "{%0,%1,%2,%3}, {%4,%5,%6,%7}, {%8,%9}, {%0,%1,%2,%3};"
        : "+f"(d[0]), "+f"(d[1]), "+f"(d[2]), "+f"(d[3])
        : "r"(a[0]), "r"(a[1]), "r"(a[2]), "r"(a[3]), "r"(bf[0]), "r"(bf[1]));
}
__device__ __forceinline__ void ldsm4(uint32_t* r, uint32_t addr) {
    asm volatile("ldmatrix.sync.aligned.m8n8.x4.shared.b16 {%0,%1,%2,%3}, [%4];"
        : "=r"(r[0]), "=r"(r[1]), "=r"(r[2]), "=r"(r[3]) : "r"(addr));
}

// ---------------------------------------------------------------------------
__global__ void __launch_bounds__(256)
stats_partial(const float* __restrict__ x, int S) {
    const int b = blockIdx.x, c = blockIdx.y;
    const int chunk = (S + NCHUNK - 1) / NCHUNK;
    const int s0 = c * chunk;
    const int s1 = min(s0 + chunk, S);
    const float* xb = x + (size_t)b * S + s0;
    const int n = s1 - s0;

    float sum = 0.f, sq = 0.f;
    int pre = (int)(((16u - (unsigned)((size_t)xb & 15u)) & 15u) >> 2);
    if (pre > n) pre = n;
    for (int i = threadIdx.x; i < pre; i += 256) { float v = xb[i]; sum += v; sq += v*v; }
    int n4 = (n - pre) >> 2;
    const float4* x4 = (const float4*)(xb + pre);
    for (int i = threadIdx.x; i < n4; i += 256) {
        float4 v = x4[i];
        sum += v.x + v.y + v.z + v.w;
        sq  += v.x*v.x + v.y*v.y + v.z*v.z + v.w*v.w;
    }
    for (int i = pre + (n4 << 2) + threadIdx.x; i < n; i += 256) { float v = xb[i]; sum += v; sq += v*v; }

    __shared__ float ssum[8], ssq[8];
    #pragma unroll
    for (int o = 16; o > 0; o >>= 1) {
        sum += __shfl_xor_sync(~0u, sum, o);
        sq  += __shfl_xor_sync(~0u, sq,  o);
    }
    int w = threadIdx.x >> 5, ln = threadIdx.x & 31;
    if (ln == 0) { ssum[w] = sum; ssq[w] = sq; }
    __syncthreads();
    if (w == 0 && ln < 8) {
        sum = ssum[ln]; sq = ssq[ln];
        #pragma unroll
        for (int o = 4; o > 0; o >>= 1) {
            sum += __shfl_xor_sync(0xffu, sum, o);
            sq  += __shfl_xor_sync(0xffu, sq,  o);
        }
        if (ln == 0) { g_psum[b*NCHUNK+c] = sum; g_psq[b*NCHUNK+c] = sq; }
    }
}

__global__ void stats_final(int S) {
    int b = threadIdx.x;
    if (b >= NB) return;
    float sum = 0.f, sq = 0.f;
    #pragma unroll
    for (int c = 0; c < NCHUNK; c++) { sum += g_psum[b*NCHUNK+c]; sq += g_psq[b*NCHUNK+c]; }
    float mu  = sum / (float)S;
    float var = sq / (float)S - mu * mu;
    g_mu[b] = mu;
    g_sd[b] = sqrtf(fmaxf(var, 0.f));
}

// ---------------------------------------------------------------------------
__global__ void prep_b_kernel(const float* __restrict__ kr,
                              const float* __restrict__ ki) {
    int idx = blockIdx.x * blockDim.x + threadIdx.x;
    if (idx >= NCHK * 256 * BP) return;
    int kk = idx % BP;
    int n  = (idx / BP) & 255;
    int c  = idx / (256 * BP);
    int k  = c * KC + kk;
    float v = 0.f;
    if (kk < KC && k < LEN)
        v = ((n < NH) ? kr : ki)[(size_t)(n & 127) * LEN + k];
    __half h = __float2half_rn(v);
    g_bh[idx] = h;
    g_bl[idx] = __float2half_rn(v - __half2float(h));
}

// ---------------------------------------------------------------------------
// Fused: frame+normalize (fp16 hi/lo) + 3xFP16 HMMA DFT (ldmatrix frags)
// grid (T/64, NB), 256 threads = 8 warps (2m x 4n); warp tile 32t x 64n.
// ---------------------------------------------------------------------------
__global__ void __launch_bounds__(256, 2)
dft_mma_kernel(const float* __restrict__ x,
               float* __restrict__ out, int S, int T) {
    extern __shared__ char smem[];
    const uint32_t smb = (uint32_t)__cvta_generic_to_shared(smem);

    const int tid  = threadIdx.x;
    const int lane = tid & 31;
    const int wid  = tid >> 5;
    const int g    = lane >> 2;
    const int q    = lane & 3;
    const int wm   = wid & 1;
    const int wn   = wid >> 1;
    const int tw   = wm * 32;
    const int nw   = wn * 64;

    const int b  = blockIdx.y;
    const int t0 = blockIdx.x * MTILE;
    const float mu  = g_mu[b];
    const float inv = 1.f / (g_sd[b] + EPSF);
    const float* xrow = x + (size_t)b * S + (size_t)t0 * SHIFT;

    // stage frames: [t][k] normalized, hi/lo split
    {
        uint32_t* fh = (uint32_t*)(smem + SM_FH);
        uint32_t* fl = (uint32_t*)(smem + SM_FL);
        for (int i = tid; i < MTILE * (FP / 2); i += 256) {
            const int t  = i / (FP / 2);
            const int kp = (i % (FP / 2)) * 2;
            const float* src = xrow + t * SHIFT + kp;
            float v0 = (src[0] - mu) * inv;
            float v1 = (src[1] - mu) * inv;
            __half h0 = __float2half_rn(v0), h1 = __float2half_rn(v1);
            __half l0 = __float2half_rn(v0 - __half2float(h0));
            __half l1 = __float2half_rn(v1 - __half2float(h1));
            fh[i] = (uint32_t)__half_as_ushort(h0) | ((uint32_t)__half_as_ushort(h1) << 16);
            fl[i] = (uint32_t)__half_as_ushort(l0) | ((uint32_t)__half_as_ushort(l1) << 16);
        }
    }

    float acc[2][8][4];
    #pragma unroll
    for (int mt = 0; mt < 2; mt++)
        #pragma unroll
        for (int nt = 0; nt < 8; nt++)
            #pragma unroll
            for (int i = 0; i < 4; i++) acc[mt][nt][i] = 0.f;

    // per-lane ldmatrix base addresses (bytes)
    // A: lanes 0-15 -> rows 0-15 (k+0), lanes 16-31 -> rows 0-15 (k+8)
    const uint32_t aAh = smb + SM_FH +
        (uint32_t)(((tw + (lane & 15)) * FP + ((lane >> 4) << 3)) * 2);
    const uint32_t aAl = aAh + (SM_FL - SM_FH);
    // B: lanes 0-7 nt_u k+0, 8-15 nt_u k+8, 16-23 nt_{u+1} k+0, 24-31 nt_{u+1} k+8
    const uint32_t aBh = smb + SM_BH +
        (uint32_t)((((lane & 7) + ((lane >> 4) << 3)) * BP + ((lane >> 3) & 1) * 8) * 2);
    const uint32_t aBl = aBh + (SM_BL - SM_BH);

    for (int c = 0; c < NCHK; c++) {
        // stage B chunk
        {
            const uint4* sbh = (const uint4*)(g_bh + c * 256 * BP);
            const uint4* sbl = (const uint4*)(g_bl + c * 256 * BP);
            uint4* dbh = (uint4*)(smem + SM_BH);
            uint4* dbl = (uint4*)(smem + SM_BL);
            #pragma unroll
            for (int i = 0; i < 7; i++) {
                dbh[tid + i * 256] = sbh[tid + i * 256];
                dbl[tid + i * 256] = sbl[tid + i * 256];
            }
        }
        __syncthreads();

        const int nsteps = (c < 4) ? 3 : 1;
        #pragma unroll
        for (int ks = 0; ks < 3; ks++) {
            if (ks >= nsteps) break;
            const uint32_t kgb = (uint32_t)((c * KC + ks * 16) * 2);  // A k offset, bytes
            const uint32_t klb = (uint32_t)((ks * 16) * 2);           // B local k offset

            uint32_t ah[2][4], al[2][4];
            ldsm4(ah[0], aAh + kgb);
            ldsm4(ah[1], aAh + kgb + 16 * FP * 2);
            ldsm4(al[0], aAl + kgb);
            ldsm4(al[1], aAl + kgb + 16 * FP * 2);

            #pragma unroll
            for (int h = 0; h < 2; h++) {
                // two x4 loads cover nt = h*4 .. h*4+3 (pairs)
                uint32_t bh4[2][4], bl4[2][4];
                #pragma unroll
                for (int p = 0; p < 2; p++) {
                    const uint32_t noff = (uint32_t)((nw + (h * 4 + p * 2) * 8) * BP * 2);
                    ldsm4(bh4[p], aBh + noff + klb);
                    ldsm4(bl4[p], aBl + noff + klb);
                }
                uint32_t bhf[4][2], blf[4][2];
                #pragma unroll
                for (int u = 0; u < 4; u++) {
                    bhf[u][0] = bh4[u >> 1][(u & 1) * 2];
                    bhf[u][1] = bh4[u >> 1][(u & 1) * 2 + 1];
                    blf[u][0] = bl4[u >> 1][(u & 1) * 2];
                    blf[u][1] = bl4[u >> 1][(u & 1) * 2 + 1];
                }
                #pragma unroll
                for (int u = 0; u < 4; u++) {
                    mma16(acc[0][h * 4 + u], ah[0], bhf[u]);
                    mma16(acc[1][h * 4 + u], ah[1], bhf[u]);
                }
                #pragma unroll
                for (int u = 0; u < 4; u++) {
                    mma16(acc[0][h * 4 + u], al[0], bhf[u]);
                    mma16(acc[1][h * 4 + u], al[1], bhf[u]);
                }
                #pragma unroll
                for (int u = 0; u < 4; u++) {
                    mma16(acc[0][h * 4 + u], ah[0], blf[u]);
                    mma16(acc[1][h * 4 + u], ah[1], blf[u]);
                }
            }
        }
        __syncthreads();
    }

    // ---- epilogue (pitch 68) ----
    float* imst = (float*)(smem + OFF_IM);
    float* vst  = (float*)(smem + OFF_V);
    float* mn   = (float*)(smem + OFF_MEAN);
    float* ivn  = (float*)(smem + OFF_INV);

    if (wn >= 2) {
        #pragma unroll
        for (int mt = 0; mt < 2; mt++)
            #pragma unroll
            for (int nt = 0; nt < 8; nt++) {
                const int ni = (wn - 2) * 64 + nt * 8 + 2 * q;
                const int t  = tw + mt * 16 + g;
                imst[ni * 68 + t]           = acc[mt][nt][0];
                imst[(ni + 1) * 68 + t]     = acc[mt][nt][1];
                imst[ni * 68 + t + 8]       = acc[mt][nt][2];
                imst[(ni + 1) * 68 + t + 8] = acc[mt][nt][3];
            }
    }
    __syncthreads();
    if (wn < 2) {
        #pragma unroll
        for (int mt = 0; mt < 2; mt++)
            #pragma unroll
            for (int nt = 0; nt < 8; nt++) {
                const int n = nw + nt * 8 + 2 * q;
                const int t = tw + mt * 16 + g;
                #pragma unroll
                for (int e = 0; e < 4; e++) {
                    const int nn = n + (e & 1);
                    const int tt = t + ((e >> 1) << 3);
                    float re = acc[mt][nt][e];
                    float im = imst[nn * 68 + tt];
                    float m2 = fmaxf(re * re + im * im, 1e-14f);
                    vst[nn * 68 + tt] = __logf(m2) * HALF_INV_LN10;
                }
            }
    }
    __syncthreads();
    if (tid < MTILE) {
        const int t = tid;
        float sum = 0.f, sq = 0.f;
        #pragma unroll 8
        for (int n = 0; n < NH; n++) {
            float v = vst[n * 68 + t];
            sum += v; sq += v * v;
        }
        const float mean = sum * (1.f / NH);
        const float var  = sq * (1.f / NH) - mean * mean;
        mn[t]  = mean;
        ivn[t] = 1.f / (sqrtf(fmaxf(var, 0.f)) + EPSF);
    }
    __syncthreads();
    for (int idx = tid; idx < NH * MTILE; idx += 256) {
        const int n = idx >> 6, t = idx & 63;
        out[((size_t)(b * NH + n)) * T + t0 + t] = (vst[n * 68 + t] - mn[t]) * ivn[t];
    }
}

// ---------------------------------------------------------------------------
extern "C" void kernel_launch(void* const* d_in, const int* in_sizes, int n_in,
                              void* d_out, int out_size) {
    const float* x  = (const float*)d_in[0];
    const float* kr = (const float*)d_in[1];
    const float* ki = (const float*)d_in[2];
    float* out = (float*)d_out;

    const int S = in_sizes[0] / NB;            // 480050
    const int T = (S - LEN) / SHIFT + 1;       // 3200

    cudaFuncSetAttribute(dft_mma_kernel, cudaFuncAttributeMaxDynamicSharedMemorySize, SMEM_TOTAL);

    stats_partial<<<dim3(NB, NCHUNK), 256>>>(x, S);
    stats_final<<<1, 64>>>(S);
    prep_b_kernel<<<(NCHK * 256 * BP + 255) / 256, 256>>>(kr, ki);
    dft_mma_kernel<<<dim3(T / MTILE, NB), 256, SMEM_TOTAL>>>(x, out, S, T);
}